// round 1
// baseline (speedup 1.0000x reference)
#include <cuda_runtime.h>
#include <math.h>
#include <stdint.h>

// ---------------- problem constants ----------------
#define T_TOK   8192          // B*S
#define DIMK    1024          // DIM == INTER == 1024
#define NE      31            // routed experts
#define NTILE_SHARED (T_TOK/64)
#define CAP     34816         // 24576 + 31*64 + 8192 = 34752, padded
#define MAXTILES (CAP/64)     // 544

// ---------------- device scratch (no allocations allowed) ----------------
__device__ int   g_cnt[NE];
__device__ int   g_fill[NE];
__device__ int   g_off[NE + 2];
__device__ int   g_ntiles;
__device__ int   g_tile_expert[MAXTILES];
__device__ int   g_tok[CAP];
__device__ float g_gate[CAP];
__device__ int   g_slot[T_TOK * 4];
__device__ int   g_tidx[T_TOK * 3];
__device__ float g_tval[T_TOK * 3];
__device__ float g_H[(size_t)CAP * DIMK];   // hidden activations (post-gelu)
__device__ float g_Y[(size_t)CAP * DIMK];   // per-assignment expert outputs (gated)

__device__ __forceinline__ float gelu_exact(float v) {
    return 0.5f * v * (1.0f + erff(v * 0.70710678118654752f));
}

// ---------------- init: reset counters + pad markers ----------------
__global__ void init_kernel() {
    int i = blockIdx.x * 256 + threadIdx.x;
    if (i < CAP) g_tok[i] = -1;
    if (i < NE)  g_cnt[i] = 0;
}

// ---------------- router: logits GEMM + softmax + top-3 ----------------
// block = 256 threads, 64 tokens per block. lane = expert (0..31, 31 = pad),
// warp w handles tokens w*8..w*8+7.
__global__ __launch_bounds__(256) void router_kernel(
    const float* __restrict__ x, const float* __restrict__ Wr,
    const float* __restrict__ br)
{
    __shared__ float xs[64][64];
    __shared__ float ws[64][32];
    int tid  = threadIdx.x;
    int t0   = blockIdx.x * 64;
    int lane = tid & 31;
    int w8   = tid >> 5;

    float acc[8] = {0.f,0.f,0.f,0.f,0.f,0.f,0.f,0.f};

    for (int k0 = 0; k0 < DIMK; k0 += 64) {
        // stage x tile: 64 tokens x 64 dims (1024 float4, 4 per thread)
        #pragma unroll
        for (int i = 0; i < 4; ++i) {
            int fid = tid + i * 256;
            int tr  = fid >> 4;
            int kq  = (fid & 15) * 4;
            *(float4*)(&xs[tr][kq]) =
                *(const float4*)(x + (size_t)(t0 + tr) * DIMK + k0 + kq);
        }
        // stage Wr tile: 64 x 32 (expert 31 padded with 0)
        #pragma unroll
        for (int i = 0; i < 8; ++i) {
            int fid = tid + i * 256;
            int kk  = fid >> 5;
            int ee  = fid & 31;
            ws[kk][ee] = (ee < NE) ? Wr[(size_t)(k0 + kk) * NE + ee] : 0.f;
        }
        __syncthreads();
        #pragma unroll 8
        for (int k = 0; k < 64; ++k) {
            float wv = ws[k][lane];
            #pragma unroll
            for (int j = 0; j < 8; ++j)
                acc[j] += xs[w8 * 8 + j][k] * wv;
        }
        __syncthreads();
    }

    float bias = (lane < NE) ? br[lane] : 0.f;

    for (int j = 0; j < 8; ++j) {
        int t = t0 + w8 * 8 + j;
        float v = (lane < NE) ? (acc[j] + bias) : -3.0e38f;
        // warp softmax over 31 experts
        float m = v;
        #pragma unroll
        for (int o = 16; o; o >>= 1)
            m = fmaxf(m, __shfl_xor_sync(0xffffffffu, m, o));
        float p = expf(v - m);
        float s = p;
        #pragma unroll
        for (int o = 16; o; o >>= 1)
            s += __shfl_xor_sync(0xffffffffu, s, o);
        p /= s;
        // top-3 (lowest index wins ties, matching top_k)
        float pv = p;
        #pragma unroll
        for (int r = 0; r < 3; ++r) {
            float mv = pv; int mi = lane;
            #pragma unroll
            for (int o = 16; o; o >>= 1) {
                float ov = __shfl_xor_sync(0xffffffffu, mv, o);
                int   oi = __shfl_xor_sync(0xffffffffu, mi, o);
                if (ov > mv || (ov == mv && oi < mi)) { mv = ov; mi = oi; }
            }
            if (lane == 0) {
                g_tidx[t * 3 + r] = mi;
                g_tval[t * 3 + r] = mv;
                atomicAdd(&g_cnt[mi], 1);
            }
            if (lane == mi) pv = -1.f;
        }
    }
}

// ---------------- scan: 64-aligned expert segments + tile->expert map ----
__global__ void scan_kernel() {
    if (threadIdx.x == 0 && blockIdx.x == 0) {
        int off = 0, tilec = 0;
        for (int e = 0; e < NE; ++e) {
            g_off[e]  = off;
            g_fill[e] = off;
            int tiles = (g_cnt[e] + 63) >> 6;
            for (int i = 0; i < tiles; ++i) g_tile_expert[tilec++] = e;
            off += tiles << 6;
        }
        g_off[NE] = off;                 // shared-expert base
        for (int i = 0; i < NTILE_SHARED; ++i) g_tile_expert[tilec++] = NE;
        g_ntiles = tilec;
        g_off[NE + 1] = off + T_TOK;
    }
}

// ---------------- fill: scatter tokens into expert segments --------------
__global__ void fill_kernel() {
    int t = blockIdx.x * 256 + threadIdx.x;
    if (t >= T_TOK) return;
    #pragma unroll
    for (int r = 0; r < 3; ++r) {
        int e   = g_tidx[t * 3 + r];
        int pos = atomicAdd(&g_fill[e], 1);
        g_tok[pos]  = t;
        g_gate[pos] = g_tval[t * 3 + r];
        g_slot[t * 4 + r] = pos;
    }
    int pos = g_off[NE] + t;   // shared expert slot, gate = 1
    g_tok[pos]  = t;
    g_gate[pos] = 1.f;
    g_slot[t * 4 + 3] = pos;
}

// ---------------- FFN GEMM 1: H = gelu(gather(x) @ W1 + b1) --------------
// tile 64x64, BK=16, 256 threads, 4x4 micro-tile
__global__ __launch_bounds__(256) void ffn1_kernel(
    const float* __restrict__ x,
    const float* __restrict__ ws1, const float* __restrict__ bs1,
    const float* __restrict__ We1, const float* __restrict__ Be1)
{
    int bx = blockIdx.x;
    if (bx >= g_ntiles) return;
    int by = blockIdx.y;
    int e  = g_tile_expert[bx];
    const float* W  = (e < NE) ? (We1 + (size_t)e * DIMK * DIMK) : ws1;
    const float* Bv = (e < NE) ? (Be1 + (size_t)e * DIMK) : bs1;

    __shared__ float As[16][68];
    __shared__ float Bs[16][64];

    int tid  = threadIdx.x;
    int aRow = tid >> 2, aK4 = tid & 3;
    int bK   = tid >> 4, bN4 = tid & 15;
    int ty   = tid >> 4, tx  = tid & 15;
    int rb   = bx * 64;

    int tok = g_tok[rb + aRow];
    const float* aPtr = x + (size_t)(tok < 0 ? 0 : tok) * DIMK + aK4 * 4;
    const float* bPtr = W + (size_t)bK * DIMK + by * 64 + bN4 * 4;

    float acc[4][4] = {};

    for (int k0 = 0; k0 < DIMK; k0 += 16) {
        float4 av = make_float4(0.f, 0.f, 0.f, 0.f);
        if (tok >= 0) av = *(const float4*)(aPtr + k0);
        float4 bv = *(const float4*)(bPtr + (size_t)k0 * DIMK);

        As[aK4 * 4 + 0][aRow] = av.x;
        As[aK4 * 4 + 1][aRow] = av.y;
        As[aK4 * 4 + 2][aRow] = av.z;
        As[aK4 * 4 + 3][aRow] = av.w;
        *(float4*)(&Bs[bK][bN4 * 4]) = bv;
        __syncthreads();

        #pragma unroll
        for (int k = 0; k < 16; ++k) {
            float4 a = *(const float4*)(&As[k][ty * 4]);
            float4 b = *(const float4*)(&Bs[k][tx * 4]);
            acc[0][0] += a.x * b.x; acc[0][1] += a.x * b.y;
            acc[0][2] += a.x * b.z; acc[0][3] += a.x * b.w;
            acc[1][0] += a.y * b.x; acc[1][1] += a.y * b.y;
            acc[1][2] += a.y * b.z; acc[1][3] += a.y * b.w;
            acc[2][0] += a.z * b.x; acc[2][1] += a.z * b.y;
            acc[2][2] += a.z * b.z; acc[2][3] += a.z * b.w;
            acc[3][0] += a.w * b.x; acc[3][1] += a.w * b.y;
            acc[3][2] += a.w * b.z; acc[3][3] += a.w * b.w;
        }
        __syncthreads();
    }

    int ncol = by * 64 + tx * 4;
    float4 bias = *(const float4*)(Bv + ncol);
    #pragma unroll
    for (int i = 0; i < 4; ++i) {
        int row = rb + ty * 4 + i;
        float4 h;
        h.x = gelu_exact(acc[i][0] + bias.x);
        h.y = gelu_exact(acc[i][1] + bias.y);
        h.z = gelu_exact(acc[i][2] + bias.z);
        h.w = gelu_exact(acc[i][3] + bias.w);
        *(float4*)(&g_H[(size_t)row * DIMK + ncol]) = h;
    }
}

// ---------------- FFN GEMM 2: Y = gate * (H @ W2 + b2) -------------------
__global__ __launch_bounds__(256) void ffn2_kernel(
    const float* __restrict__ ws2, const float* __restrict__ bs2,
    const float* __restrict__ We2, const float* __restrict__ Be2)
{
    int bx = blockIdx.x;
    if (bx >= g_ntiles) return;
    int by = blockIdx.y;
    int e  = g_tile_expert[bx];
    const float* W  = (e < NE) ? (We2 + (size_t)e * DIMK * DIMK) : ws2;
    const float* Bv = (e < NE) ? (Be2 + (size_t)e * DIMK) : bs2;

    __shared__ float As[16][68];
    __shared__ float Bs[16][64];

    int tid  = threadIdx.x;
    int aRow = tid >> 2, aK4 = tid & 3;
    int bK   = tid >> 4, bN4 = tid & 15;
    int ty   = tid >> 4, tx  = tid & 15;
    int rb   = bx * 64;

    const float* aPtr = g_H + (size_t)(rb + aRow) * DIMK + aK4 * 4;
    const float* bPtr = W + (size_t)bK * DIMK + by * 64 + bN4 * 4;

    float acc[4][4] = {};

    for (int k0 = 0; k0 < DIMK; k0 += 16) {
        float4 av = *(const float4*)(aPtr + k0);
        float4 bv = *(const float4*)(bPtr + (size_t)k0 * DIMK);

        As[aK4 * 4 + 0][aRow] = av.x;
        As[aK4 * 4 + 1][aRow] = av.y;
        As[aK4 * 4 + 2][aRow] = av.z;
        As[aK4 * 4 + 3][aRow] = av.w;
        *(float4*)(&Bs[bK][bN4 * 4]) = bv;
        __syncthreads();

        #pragma unroll
        for (int k = 0; k < 16; ++k) {
            float4 a = *(const float4*)(&As[k][ty * 4]);
            float4 b = *(const float4*)(&Bs[k][tx * 4]);
            acc[0][0] += a.x * b.x; acc[0][1] += a.x * b.y;
            acc[0][2] += a.x * b.z; acc[0][3] += a.x * b.w;
            acc[1][0] += a.y * b.x; acc[1][1] += a.y * b.y;
            acc[1][2] += a.y * b.z; acc[1][3] += a.y * b.w;
            acc[2][0] += a.z * b.x; acc[2][1] += a.z * b.y;
            acc[2][2] += a.z * b.z; acc[2][3] += a.z * b.w;
            acc[3][0] += a.w * b.x; acc[3][1] += a.w * b.y;
            acc[3][2] += a.w * b.z; acc[3][3] += a.w * b.w;
        }
        __syncthreads();
    }

    int ncol = by * 64 + tx * 4;
    float4 bias = *(const float4*)(Bv + ncol);
    #pragma unroll
    for (int i = 0; i < 4; ++i) {
        int row = rb + ty * 4 + i;
        float g = g_gate[row];
        float4 o;
        o.x = g * (acc[i][0] + bias.x);
        o.y = g * (acc[i][1] + bias.y);
        o.z = g * (acc[i][2] + bias.z);
        o.w = g * (acc[i][3] + bias.w);
        *(float4*)(&g_Y[(size_t)row * DIMK + ncol]) = o;
    }
}

// ---------------- finalize: out = x + sum of the token's 4 slot rows -----
__global__ void finalize_kernel(const float* __restrict__ x,
                                float* __restrict__ out)
{
    int idx = blockIdx.x * 256 + threadIdx.x;   // 0 .. T_TOK*256-1
    int t = idx >> 8;
    int q = (idx & 255) * 4;
    float4 r = *(const float4*)(x + (size_t)t * DIMK + q);
    #pragma unroll
    for (int k = 0; k < 4; ++k) {
        int s = g_slot[t * 4 + k];
        float4 v = *(const float4*)(&g_Y[(size_t)s * DIMK + q]);
        r.x += v.x; r.y += v.y; r.z += v.z; r.w += v.w;
    }
    *(float4*)(out + (size_t)t * DIMK + q) = r;
}

// ---------------- launch ----------------
extern "C" void kernel_launch(void* const* d_in, const int* in_sizes, int n_in,
                              void* d_out, int out_size)
{
    const float* x   = (const float*)d_in[0];
    const float* ws1 = (const float*)d_in[1];
    const float* bs1 = (const float*)d_in[2];
    const float* ws2 = (const float*)d_in[3];
    const float* bs2 = (const float*)d_in[4];
    const float* We1 = (const float*)d_in[5];
    const float* Be1 = (const float*)d_in[6];
    const float* We2 = (const float*)d_in[7];
    const float* Be2 = (const float*)d_in[8];
    const float* Wr  = (const float*)d_in[9];
    const float* br  = (const float*)d_in[10];
    float* out = (float*)d_out;

    init_kernel<<<(CAP + 255) / 256, 256>>>();
    router_kernel<<<T_TOK / 64, 256>>>(x, Wr, br);
    scan_kernel<<<1, 32>>>();
    fill_kernel<<<(T_TOK + 255) / 256, 256>>>();

    dim3 g(MAXTILES, DIMK / 64);
    ffn1_kernel<<<g, 256>>>(x, ws1, bs1, We1, Be1);
    ffn2_kernel<<<g, 256>>>(ws2, bs2, We2, Be2);

    finalize_kernel<<<T_TOK, 256>>>(x, out);
}

// round 2
// speedup vs baseline: 2.8854x; 2.8854x over previous
#include <cuda_runtime.h>
#include <math.h>
#include <stdint.h>

// ---------------- problem constants ----------------
#define T_TOK   8192          // B*S
#define DIMK    1024          // DIM == INTER == 1024
#define NE      31            // routed experts
#define NTILE_SHARED (T_TOK/64)
#define CAP     34816
#define MAXTILES (CAP/64)     // 544

// GEMM tile config
#define BM 64
#define BN 256
#define BKK 32
#define APAD 36               // As row stride (floats)
#define BPAD 264              // Bs row stride (floats)
#define SMEM_FLOATS (2*BM*APAD + 2*BKK*BPAD)   // 4608 + 16896 = 21504
#define SMEM_BYTES  (SMEM_FLOATS * 4)          // 86016

// ---------------- device scratch ----------------
__device__ int   g_cnt[NE];
__device__ int   g_fill[NE];
__device__ int   g_off[NE + 2];
__device__ int   g_ntiles;
__device__ int   g_tile_expert[MAXTILES];
__device__ int   g_tok[CAP];
__device__ float g_gate[CAP];
__device__ int   g_slot[T_TOK * 4];
__device__ int   g_tidx[T_TOK * 3];
__device__ float g_tval[T_TOK * 3];
__device__ float g_H[(size_t)CAP * DIMK];
__device__ float g_Y[(size_t)CAP * DIMK];

__device__ __forceinline__ float gelu_exact(float v) {
    return 0.5f * v * (1.0f + erff(v * 0.70710678118654752f));
}

__device__ __forceinline__ float to_tf32(float v) {
    float r;
    asm("cvt.rna.tf32.f32 %0, %1;" : "=f"(r) : "f"(v));
    return r;
}
__device__ __forceinline__ float4 tf4(float4 v) {
    return make_float4(to_tf32(v.x), to_tf32(v.y), to_tf32(v.z), to_tf32(v.w));
}

__device__ __forceinline__ void mma_tf32(float c[4], const unsigned a[4],
                                         const unsigned b[2]) {
    asm volatile(
        "mma.sync.aligned.m16n8k8.row.col.f32.tf32.tf32.f32 "
        "{%0,%1,%2,%3}, {%4,%5,%6,%7}, {%8,%9}, {%0,%1,%2,%3};\n"
        : "+f"(c[0]), "+f"(c[1]), "+f"(c[2]), "+f"(c[3])
        : "r"(a[0]), "r"(a[1]), "r"(a[2]), "r"(a[3]), "r"(b[0]), "r"(b[1]));
}

// ---------------- init ----------------
__global__ void init_kernel() {
    int i = blockIdx.x * 256 + threadIdx.x;
    if (i < CAP) g_tok[i] = -1;
    if (i < NE)  g_cnt[i] = 0;
}

// ---------------- router ----------------
__global__ __launch_bounds__(256) void router_kernel(
    const float* __restrict__ x, const float* __restrict__ Wr,
    const float* __restrict__ br)
{
    __shared__ float xs[64][64];
    __shared__ float ws[64][32];
    int tid  = threadIdx.x;
    int t0   = blockIdx.x * 64;
    int lane = tid & 31;
    int w8   = tid >> 5;

    float acc[8] = {0.f,0.f,0.f,0.f,0.f,0.f,0.f,0.f};

    for (int k0 = 0; k0 < DIMK; k0 += 64) {
        #pragma unroll
        for (int i = 0; i < 4; ++i) {
            int fid = tid + i * 256;
            int tr  = fid >> 4;
            int kq  = (fid & 15) * 4;
            *(float4*)(&xs[tr][kq]) =
                *(const float4*)(x + (size_t)(t0 + tr) * DIMK + k0 + kq);
        }
        #pragma unroll
        for (int i = 0; i < 8; ++i) {
            int fid = tid + i * 256;
            int kk  = fid >> 5;
            int ee  = fid & 31;
            ws[kk][ee] = (ee < NE) ? Wr[(size_t)(k0 + kk) * NE + ee] : 0.f;
        }
        __syncthreads();
        #pragma unroll 8
        for (int k = 0; k < 64; ++k) {
            float wv = ws[k][lane];
            #pragma unroll
            for (int j = 0; j < 8; ++j)
                acc[j] += xs[w8 * 8 + j][k] * wv;
        }
        __syncthreads();
    }

    float bias = (lane < NE) ? br[lane] : 0.f;

    for (int j = 0; j < 8; ++j) {
        int t = t0 + w8 * 8 + j;
        float v = (lane < NE) ? (acc[j] + bias) : -3.0e38f;
        float m = v;
        #pragma unroll
        for (int o = 16; o; o >>= 1)
            m = fmaxf(m, __shfl_xor_sync(0xffffffffu, m, o));
        float p = expf(v - m);
        float s = p;
        #pragma unroll
        for (int o = 16; o; o >>= 1)
            s += __shfl_xor_sync(0xffffffffu, s, o);
        p /= s;
        float pv = p;
        #pragma unroll
        for (int r = 0; r < 3; ++r) {
            float mv = pv; int mi = lane;
            #pragma unroll
            for (int o = 16; o; o >>= 1) {
                float ov = __shfl_xor_sync(0xffffffffu, mv, o);
                int   oi = __shfl_xor_sync(0xffffffffu, mi, o);
                if (ov > mv || (ov == mv && oi < mi)) { mv = ov; mi = oi; }
            }
            if (lane == 0) {
                g_tidx[t * 3 + r] = mi;
                g_tval[t * 3 + r] = mv;
                atomicAdd(&g_cnt[mi], 1);
            }
            if (lane == mi) pv = -1.f;
        }
    }
}

// ---------------- scan ----------------
__global__ void scan_kernel() {
    if (threadIdx.x == 0 && blockIdx.x == 0) {
        int off = 0, tilec = 0;
        for (int e = 0; e < NE; ++e) {
            g_off[e]  = off;
            g_fill[e] = off;
            int tiles = (g_cnt[e] + 63) >> 6;
            for (int i = 0; i < tiles; ++i) g_tile_expert[tilec++] = e;
            off += tiles << 6;
        }
        g_off[NE] = off;
        for (int i = 0; i < NTILE_SHARED; ++i) g_tile_expert[tilec++] = NE;
        g_ntiles = tilec;
        g_off[NE + 1] = off + T_TOK;
    }
}

// ---------------- fill ----------------
__global__ void fill_kernel() {
    int t = blockIdx.x * 256 + threadIdx.x;
    if (t >= T_TOK) return;
    #pragma unroll
    for (int r = 0; r < 3; ++r) {
        int e   = g_tidx[t * 3 + r];
        int pos = atomicAdd(&g_fill[e], 1);
        g_tok[pos]  = t;
        g_gate[pos] = g_tval[t * 3 + r];
        g_slot[t * 4 + r] = pos;
    }
    int pos = g_off[NE] + t;
    g_tok[pos]  = t;
    g_gate[pos] = 1.f;
    g_slot[t * 4 + 3] = pos;
}

// ---------------- tensor-core FFN GEMM ----------------
// MODE 0: H = gelu(gather(x) @ W1 + b1)   (A gathered via g_tok)
// MODE 1: Y = gate * (H @ W2 + b2)        (A = g_H rows)
// grid = (DIMK/BN, MAXTILES), block = 256 (8 warps: 2M x 4N, warp tile 32x64)
template <int MODE>
__global__ __launch_bounds__(256, 1) void ffn_mma_kernel(
    const float* __restrict__ x,
    const float* __restrict__ wsh, const float* __restrict__ bsh,
    const float* __restrict__ Wex, const float* __restrict__ Bex)
{
    int tile = blockIdx.y;
    if (tile >= g_ntiles) return;
    int e  = g_tile_expert[tile];
    const float* W  = (e < NE) ? (Wex + (size_t)e * DIMK * DIMK) : wsh;
    const float* Bv = (e < NE) ? (Bex + (size_t)e * DIMK) : bsh;

    extern __shared__ float smem[];
    float* AsBase = smem;                      // [2][BM][APAD]
    float* BsBase = smem + 2 * BM * APAD;      // [2][BKK][BPAD]

    const int tid  = threadIdx.x;
    const int lane = tid & 31;
    const int warp = tid >> 5;
    const int wm   = (warp & 1) * 32;          // warp M offset in tile
    const int wn   = (warp >> 1) * 64;         // warp N offset in tile
    const int qr   = lane >> 2;                // groupID
    const int qc   = lane & 3;                 // threadInGroup

    const int rb = tile * 64;                  // slot-row base
    const int nb = blockIdx.x * BN;            // N base

    // ---- A source pointers (2 rows per thread) ----
    const int ar = tid >> 3;                   // 0..31
    const int ac = (tid & 7) * 4;
    const float* aP0;
    const float* aP1;
    bool av0 = true, av1 = true;
    if (MODE == 0) {
        int t0 = g_tok[rb + ar];
        int t1 = g_tok[rb + ar + 32];
        av0 = (t0 >= 0); av1 = (t1 >= 0);
        aP0 = x + (size_t)(av0 ? t0 : 0) * DIMK + ac;
        aP1 = x + (size_t)(av1 ? t1 : 0) * DIMK + ac;
    } else {
        aP0 = g_H + (size_t)(rb + ar) * DIMK + ac;
        aP1 = g_H + (size_t)(rb + ar + 32) * DIMK + ac;
    }
    // B source: 8 float4 per thread per K-step
    const int bk0 = tid >> 6;                  // 0..3 (step 4 per i)
    const int bc  = (tid & 63) * 4;

    float4 aR[2];
    float4 bR[8];
    const float4 f4z = make_float4(0.f, 0.f, 0.f, 0.f);

    // prologue: load k0 = 0
    aR[0] = av0 ? *(const float4*)(aP0) : f4z;
    aR[1] = av1 ? *(const float4*)(aP1) : f4z;
    #pragma unroll
    for (int i = 0; i < 8; ++i)
        bR[i] = *(const float4*)(W + (size_t)(bk0 + i * 4) * DIMK + nb + bc);

    {
        float* As = AsBase;
        float* Bs = BsBase;
        *(float4*)(As + ar * APAD + ac)        = tf4(aR[0]);
        *(float4*)(As + (ar + 32) * APAD + ac) = tf4(aR[1]);
        #pragma unroll
        for (int i = 0; i < 8; ++i)
            *(float4*)(Bs + (bk0 + i * 4) * BPAD + bc) = tf4(bR[i]);
    }
    __syncthreads();

    float acc[2][8][4];
    #pragma unroll
    for (int mt = 0; mt < 2; ++mt)
        #pragma unroll
        for (int nt = 0; nt < 8; ++nt)
            #pragma unroll
            for (int q = 0; q < 4; ++q) acc[mt][nt][q] = 0.f;

    int cur = 0;
    for (int k0 = 0; k0 < DIMK; k0 += BKK) {
        bool more = (k0 + BKK < DIMK);
        if (more) {
            int kn = k0 + BKK;
            aR[0] = av0 ? *(const float4*)(aP0 + kn) : f4z;
            aR[1] = av1 ? *(const float4*)(aP1 + kn) : f4z;
            #pragma unroll
            for (int i = 0; i < 8; ++i)
                bR[i] = *(const float4*)(W + (size_t)(kn + bk0 + i * 4) * DIMK + nb + bc);
        }

        const float* Ac = AsBase + cur * BM * APAD;
        const float* Bc = BsBase + cur * BKK * BPAD;

        #pragma unroll
        for (int kq = 0; kq < BKK; kq += 8) {
            unsigned a[2][4], b[8][2];
            #pragma unroll
            for (int mt = 0; mt < 2; ++mt) {
                const float* ap = Ac + (size_t)(wm + mt * 16 + qr) * APAD + kq + qc;
                a[mt][0] = __float_as_uint(ap[0]);
                a[mt][1] = __float_as_uint(ap[8 * APAD]);
                a[mt][2] = __float_as_uint(ap[4]);
                a[mt][3] = __float_as_uint(ap[8 * APAD + 4]);
            }
            #pragma unroll
            for (int nt = 0; nt < 8; ++nt) {
                const float* bp = Bc + (size_t)(kq + qc) * BPAD + wn + nt * 8 + qr;
                b[nt][0] = __float_as_uint(bp[0]);
                b[nt][1] = __float_as_uint(bp[4 * BPAD]);
            }
            #pragma unroll
            for (int mt = 0; mt < 2; ++mt)
                #pragma unroll
                for (int nt = 0; nt < 8; ++nt)
                    mma_tf32(acc[mt][nt], a[mt], b[nt]);
        }

        if (more) {
            float* As = AsBase + (cur ^ 1) * BM * APAD;
            float* Bs = BsBase + (cur ^ 1) * BKK * BPAD;
            *(float4*)(As + ar * APAD + ac)        = tf4(aR[0]);
            *(float4*)(As + (ar + 32) * APAD + ac) = tf4(aR[1]);
            #pragma unroll
            for (int i = 0; i < 8; ++i)
                *(float4*)(Bs + (bk0 + i * 4) * BPAD + bc) = tf4(bR[i]);
            __syncthreads();
            cur ^= 1;
        }
    }

    // ---- epilogue ----
    #pragma unroll
    for (int nt = 0; nt < 8; ++nt) {
        int gcol = nb + wn + nt * 8 + 2 * qc;
        float b0v = Bv[gcol];
        float b1v = Bv[gcol + 1];
        #pragma unroll
        for (int mt = 0; mt < 2; ++mt) {
            int r0 = rb + wm + mt * 16 + qr;
            int r1 = r0 + 8;
            float c00 = acc[mt][nt][0] + b0v;
            float c01 = acc[mt][nt][1] + b1v;
            float c10 = acc[mt][nt][2] + b0v;
            float c11 = acc[mt][nt][3] + b1v;
            if (MODE == 0) {
                float2 v0 = make_float2(gelu_exact(c00), gelu_exact(c01));
                float2 v1 = make_float2(gelu_exact(c10), gelu_exact(c11));
                *(float2*)(&g_H[(size_t)r0 * DIMK + gcol]) = v0;
                *(float2*)(&g_H[(size_t)r1 * DIMK + gcol]) = v1;
            } else {
                float g0 = g_gate[r0];
                float g1 = g_gate[r1];
                float2 v0 = make_float2(g0 * c00, g0 * c01);
                float2 v1 = make_float2(g1 * c10, g1 * c11);
                *(float2*)(&g_Y[(size_t)r0 * DIMK + gcol]) = v0;
                *(float2*)(&g_Y[(size_t)r1 * DIMK + gcol]) = v1;
            }
        }
    }
}

// ---------------- finalize ----------------
__global__ void finalize_kernel(const float* __restrict__ x,
                                float* __restrict__ out)
{
    int idx = blockIdx.x * 256 + threadIdx.x;
    int t = idx >> 8;
    int q = (idx & 255) * 4;
    float4 r = *(const float4*)(x + (size_t)t * DIMK + q);
    #pragma unroll
    for (int k = 0; k < 4; ++k) {
        int s = g_slot[t * 4 + k];
        float4 v = *(const float4*)(&g_Y[(size_t)s * DIMK + q]);
        r.x += v.x; r.y += v.y; r.z += v.z; r.w += v.w;
    }
    *(float4*)(out + (size_t)t * DIMK + q) = r;
}

// ---------------- launch ----------------
extern "C" void kernel_launch(void* const* d_in, const int* in_sizes, int n_in,
                              void* d_out, int out_size)
{
    const float* x   = (const float*)d_in[0];
    const float* ws1 = (const float*)d_in[1];
    const float* bs1 = (const float*)d_in[2];
    const float* ws2 = (const float*)d_in[3];
    const float* bs2 = (const float*)d_in[4];
    const float* We1 = (const float*)d_in[5];
    const float* Be1 = (const float*)d_in[6];
    const float* We2 = (const float*)d_in[7];
    const float* Be2 = (const float*)d_in[8];
    const float* Wr  = (const float*)d_in[9];
    const float* br  = (const float*)d_in[10];
    float* out = (float*)d_out;

    static bool attr_done = false;
    if (!attr_done) {
        cudaFuncSetAttribute(ffn_mma_kernel<0>,
                             cudaFuncAttributeMaxDynamicSharedMemorySize, SMEM_BYTES);
        cudaFuncSetAttribute(ffn_mma_kernel<1>,
                             cudaFuncAttributeMaxDynamicSharedMemorySize, SMEM_BYTES);
        attr_done = true;
    }

    init_kernel<<<(CAP + 255) / 256, 256>>>();
    router_kernel<<<T_TOK / 64, 256>>>(x, Wr, br);
    scan_kernel<<<1, 32>>>();
    fill_kernel<<<(T_TOK + 255) / 256, 256>>>();

    dim3 g(DIMK / BN, MAXTILES);
    ffn_mma_kernel<0><<<g, 256, SMEM_BYTES>>>(x, ws1, bs1, We1, Be1);
    ffn_mma_kernel<1><<<g, 256, SMEM_BYTES>>>(x, ws2, bs2, We2, Be2);

    finalize_kernel<<<T_TOK, 256>>>(x, out);
}